// round 4
// baseline (speedup 1.0000x reference)
#include <cuda_runtime.h>
#include <cstdint>

#define NN   50000
#define NE   600000
#define ETOT 650000          // NE + NN self loops
#define CH   128
#define NL   6
#define NEG  0.2f
#define INVN (1.0f/50000.0f)
#define NBLK_SCAN 196        // ceil(50000/256)
#define GEMM_CTAS 391        // ceil(50000/128)
#define WTOT (NL*128*128)    // 98304

// ---------------- scratch (static __device__ arrays, no allocation) ----------------
__device__ float d_bufA[(size_t)NN*CH];   // holds y3 residual
__device__ float d_bufB[(size_t)NN*CH];   // holds y1 residual
__device__ float d_bufG[(size_t)NN*CH];   // pre-BN GAT output of current layer
__device__ float d_hlin[(size_t)NN*CH];
__device__ float d_asrc[NN*4];
__device__ float d_adst[NN*4];
__device__ int   d_deg[NN];
__device__ int   d_rowptr[NN+1];
__device__ int   d_colsrc[ETOT];
__device__ int   d_bsums[256];
__device__ float d_bnsum[NL*CH];
__device__ float d_bnsq[NL*CH];
// W split into tf32 hi/lo, pre-reordered into the GEMM smem image layout
__device__ float d_whi[WTOT];
__device__ float d_wlo[WTOT];

// ---------------- helpers ----------------
__device__ __forceinline__ float leaky(float x) {
    return fmaxf(x, 0.f) + NEG * fminf(x, 0.f);
}
__device__ __forceinline__ uint32_t f2tf32(float x) {
    uint32_t r;
    asm("cvt.rna.tf32.f32 %0, %1;" : "=r"(r) : "f"(x));
    return r;
}
__device__ __forceinline__ void mma8(float* c, uint32_t a0, uint32_t a1,
                                     uint32_t a2, uint32_t a3,
                                     uint32_t b0, uint32_t b1) {
    asm volatile(
        "mma.sync.aligned.m16n8k8.row.col.f32.tf32.tf32.f32 "
        "{%0,%1,%2,%3}, {%4,%5,%6,%7}, {%8,%9}, {%0,%1,%2,%3};"
        : "+f"(c[0]), "+f"(c[1]), "+f"(c[2]), "+f"(c[3])
        : "r"(a0), "r"(a1), "r"(a2), "r"(a3), "r"(b0), "r"(b1));
}

// ---------------- init: zero counters + split/reorder W (once) ----------------
__global__ void k_init(const float* __restrict__ Ws) {
    int i = blockIdx.x * 256 + threadIdx.x;     // grid 384 -> 98304 threads
    if (i < NN) d_deg[i] = 0;
    if (i < NL*CH) { d_bnsum[i] = 0.f; d_bnsq[i] = 0.f; }
    if (i == 0) d_rowptr[NN] = ETOT;
    if (i < WTOT) {
        int l = i >> 14, rem = i & 16383;
        int k = rem >> 7, n = rem & 127;
        float v = Ws[i];
        uint32_t hb = f2tf32(v);
        uint32_t lb = f2tf32(v - __uint_as_float(hb));
        int pos = l * 16384 + n * 128 + ((k >> 5) << 5)
                + (((k >> 3) & 3) << 3) + ((k & 3) << 1) + ((k >> 2) & 1);
        d_whi[pos] = __uint_as_float(hb);
        d_wlo[pos] = __uint_as_float(lb);
    }
}

// ---------------- CSR build (by destination) ----------------
__global__ void k_count(const int* __restrict__ ei) {
    int e = blockIdx.x * blockDim.x + threadIdx.x;
    if (e >= ETOT) return;
    int dst = (e < NE) ? ei[NE + e] : (e - NE);
    atomicAdd(&d_deg[dst], 1);
}

__global__ void k_scan_reduce() {
    __shared__ int s[256];
    int i = blockIdx.x * 256 + threadIdx.x;
    s[threadIdx.x] = (i < NN) ? d_deg[i] : 0;
    __syncthreads();
    for (int off = 128; off; off >>= 1) {
        if (threadIdx.x < off) s[threadIdx.x] += s[threadIdx.x + off];
        __syncthreads();
    }
    if (threadIdx.x == 0) d_bsums[blockIdx.x] = s[0];
}

__global__ void k_scan_write() {
    __shared__ int s[256];
    __shared__ int soff[256];
    int tid = threadIdx.x;
    int i = blockIdx.x * 256 + tid;
    int v = (i < NN) ? d_deg[i] : 0;
    soff[tid] = (tid < blockIdx.x) ? d_bsums[tid] : 0;
    s[tid] = v;
    __syncthreads();
    for (int off = 128; off; off >>= 1) {
        if (tid < off) soff[tid] += soff[tid + off];
        __syncthreads();
    }
    for (int off = 1; off < 256; off <<= 1) {
        int t = (tid >= off) ? s[tid - off] : 0;
        __syncthreads();
        s[tid] += t;
        __syncthreads();
    }
    if (i < NN) {
        d_rowptr[i] = soff[0] + s[tid] - v;
        d_deg[i] = 0;
    }
}

__global__ void k_scatter(const int* __restrict__ ei) {
    int e = blockIdx.x * blockDim.x + threadIdx.x;
    if (e >= ETOT) return;
    int src, dst;
    if (e < NE) { src = ei[e]; dst = ei[NE + e]; }
    else        { src = dst = e - NE; }
    int pos = d_rowptr[dst] + atomicAdd(&d_deg[dst], 1);
    d_colsrc[pos] = src;
}

// ---------------- tensor-core GEMM (mma.sync tf32, 3-term) ----------------
// Fused: input-side BN+ReLU(+residual) of the PREVIOUS layer, alpha epilogue.
// smem floats: Ahi[0,5120) Alo[5120,10240) Bhi[10240,15360) Blo[15360,20480)
//   attS[20480] attD[20608] sc[20736] sh[20864]  -> 20992 floats = 83968 B
#define GSM_BYTES  83968

__global__ void __launch_bounds__(256, 1)
k_gemm_tc(const float* __restrict__ Ain, const float* __restrict__ Whi,
          const float* __restrict__ Wlo,
          const float* __restrict__ attS, const float* __restrict__ attD,
          const float* __restrict__ bsum, const float* __restrict__ bsq,
          const float* __restrict__ gamma, const float* __restrict__ beta,
          const float* __restrict__ skip, float* __restrict__ writeY) {
    extern __shared__ float smf[];
    float2* A2h = (float2*)smf;
    float2* B2h = (float2*)(smf + 10240);
    float2* B2l = (float2*)(smf + 15360);
    float*  sAt = smf + 20480;
    float*  dAt = smf + 20608;
    float*  sc  = smf + 20736;
    float*  sh  = smf + 20864;

    int tid = threadIdx.x;
    int lane = tid & 31, g = lane >> 2, t = lane & 3;
    int w = tid >> 5, wm = w >> 1, wn = w & 1;
    int bm = blockIdx.x * 128;

    if (tid < 128) sAt[tid] = attS[tid];
    else           dAt[tid - 128] = attD[tid - 128];
    if (bsum != 0 && tid < 128) {
        float mu  = bsum[tid] * INVN;
        float var = bsq[tid] * INVN - mu * mu;
        float r = rsqrtf(var + 1e-5f);
        float gg = gamma[tid] * r;
        sc[tid] = gg;
        sh[tid] = beta[tid] - gg * mu;
    }
    if (bsum != 0) __syncthreads();

    float cfr[2][8][4];
#pragma unroll
    for (int i = 0; i < 2; i++)
#pragma unroll
        for (int j = 0; j < 8; j++)
#pragma unroll
            for (int q = 0; q < 4; q++) cfr[i][j][q] = 0.f;

    for (int kc = 0; kc < 4; kc++) {
        // ---- stage A chunk [128 x 32] with fused BN/ReLU/skip ----
#pragma unroll
        for (int it = 0; it < 4; it++) {
            int f = tid + it * 256;          // 1024 float4s
            int row = f >> 3, j = f & 7;
            int gr = bm + row;
            float4 v = make_float4(0.f, 0.f, 0.f, 0.f);
            if (gr < NN) {
                size_t off = (size_t)gr * 128 + kc * 32 + j * 4;
                v = *(const float4*)(Ain + off);
                if (bsum != 0) {
                    int ch = kc * 32 + j * 4;
                    v.x = v.x * sc[ch+0] + sh[ch+0];
                    v.y = v.y * sc[ch+1] + sh[ch+1];
                    v.z = v.z * sc[ch+2] + sh[ch+2];
                    v.w = v.w * sc[ch+3] + sh[ch+3];
                    if (skip) {
                        float4 s4 = *(const float4*)(skip + off);
                        v.x += s4.x; v.y += s4.y; v.z += s4.z; v.w += s4.w;
                    }
                    v.x = fmaxf(v.x, 0.f); v.y = fmaxf(v.y, 0.f);
                    v.z = fmaxf(v.z, 0.f); v.w = fmaxf(v.w, 0.f);
                    if (writeY) *(float4*)(writeY + off) = v;
                }
            }
            int ks = j >> 1, half = j & 1;
            float* ph = smf + row * 40 + ks * 8 + half;          // hi
            float* pl = ph + 5120;                               // lo
            float vv[4] = {v.x, v.y, v.z, v.w};
#pragma unroll
            for (int cc = 0; cc < 4; cc++) {
                uint32_t hb = f2tf32(vv[cc]);
                ph[cc * 2] = __uint_as_float(hb);
                pl[cc * 2] = __uint_as_float(f2tf32(vv[cc] - __uint_as_float(hb)));
            }
        }
        // ---- stage B chunk: pre-imaged, straight float4 copy ----
#pragma unroll
        for (int it = 0; it < 4; it++) {
            int f = tid + it * 256;          // 1024 float4s
            int n = f >> 3, q = f & 7;
            int gi = n * 32 + kc * 8 + q;
            float4 h4 = ((const float4*)Whi)[gi];
            float4 l4 = ((const float4*)Wlo)[gi];
            *(float4*)(smf + 10240 + n * 40 + q * 4) = h4;
            *(float4*)(smf + 15360 + n * 40 + q * 4) = l4;
        }
        __syncthreads();

        // ---- compute 4 ksteps ----
#pragma unroll
        for (int ks = 0; ks < 4; ks++) {
            float2 ah[2][2], al[2][2];
#pragma unroll
            for (int mt = 0; mt < 2; mt++) {
                int r0 = wm * 32 + mt * 16 + g;
                ah[mt][0] = A2h[r0 * 20 + ks * 4 + t];
                ah[mt][1] = A2h[(r0 + 8) * 20 + ks * 4 + t];
                al[mt][0] = ((float2*)(smf + 5120))[r0 * 20 + ks * 4 + t];
                al[mt][1] = ((float2*)(smf + 5120))[(r0 + 8) * 20 + ks * 4 + t];
            }
#pragma unroll
            for (int nt = 0; nt < 8; nt++) {
                int n = wn * 64 + nt * 8 + g;
                float2 bh = B2h[n * 20 + ks * 4 + t];
                float2 bl = B2l[n * 20 + ks * 4 + t];
                uint32_t bh0 = __float_as_uint(bh.x), bh1 = __float_as_uint(bh.y);
                uint32_t bl0 = __float_as_uint(bl.x), bl1 = __float_as_uint(bl.y);
#pragma unroll
                for (int mt = 0; mt < 2; mt++) {
                    uint32_t a0 = __float_as_uint(ah[mt][0].x);
                    uint32_t a1 = __float_as_uint(ah[mt][1].x);
                    uint32_t a2 = __float_as_uint(ah[mt][0].y);
                    uint32_t a3 = __float_as_uint(ah[mt][1].y);
                    mma8(cfr[mt][nt], a0, a1, a2, a3, bh0, bh1);   // hi*hi
                    mma8(cfr[mt][nt], a0, a1, a2, a3, bl0, bl1);   // hi*lo
                    uint32_t l0 = __float_as_uint(al[mt][0].x);
                    uint32_t l1 = __float_as_uint(al[mt][1].x);
                    uint32_t l2 = __float_as_uint(al[mt][0].y);
                    uint32_t l3 = __float_as_uint(al[mt][1].y);
                    mma8(cfr[mt][nt], l0, l1, l2, l3, bh0, bh1);   // lo*hi
                }
            }
        }
        __syncthreads();
    }

    // ---- epilogue: store h + fused per-head alpha dots ----
#pragma unroll
    for (int mt = 0; mt < 2; mt++) {
#pragma unroll
        for (int rr = 0; rr < 2; rr++) {
            int row = bm + wm * 32 + mt * 16 + rr * 8 + g;
            float psA = 0.f, psB = 0.f, pdA = 0.f, pdB = 0.f;
#pragma unroll
            for (int nt = 0; nt < 8; nt++) {
                float c0 = cfr[mt][nt][rr * 2 + 0];
                float c1 = cfr[mt][nt][rr * 2 + 1];
                int col0 = wn * 64 + nt * 8 + 2 * t;
                if (row < NN)
                    *(float2*)(d_hlin + (size_t)row * 128 + col0) = make_float2(c0, c1);
                float s0 = sAt[col0], s1 = sAt[col0 + 1];
                float q0 = dAt[col0], q1 = dAt[col0 + 1];
                if (nt < 4) { psA += c0 * s0 + c1 * s1; pdA += c0 * q0 + c1 * q1; }
                else        { psB += c0 * s0 + c1 * s1; pdB += c0 * q0 + c1 * q1; }
            }
            psA += __shfl_down_sync(0xffffffffu, psA, 2, 4);
            psA += __shfl_down_sync(0xffffffffu, psA, 1, 4);
            psB += __shfl_down_sync(0xffffffffu, psB, 2, 4);
            psB += __shfl_down_sync(0xffffffffu, psB, 1, 4);
            pdA += __shfl_down_sync(0xffffffffu, pdA, 2, 4);
            pdA += __shfl_down_sync(0xffffffffu, pdA, 1, 4);
            pdB += __shfl_down_sync(0xffffffffu, pdB, 2, 4);
            pdB += __shfl_down_sync(0xffffffffu, pdB, 1, 4);
            if (t == 0 && row < NN) {
                int h0 = wn * 2;
                d_asrc[row * 4 + h0]     = psA;
                d_asrc[row * 4 + h0 + 1] = psB;
                d_adst[row * 4 + h0]     = pdA;
                d_adst[row * 4 + h0 + 1] = pdB;
            }
        }
    }
}

// ---------------- GAT aggregation (warp per dst) + BN stats ----------------
__global__ void k_agg(const float* __restrict__ bias_l,
                      float* __restrict__ bnsum, float* __restrict__ bnsq) {
    __shared__ int   s_src[8][32];
    __shared__ float s_w[8][128];
    __shared__ float s_s1[128], s_s2[128];
    int tid = threadIdx.x;
    if (tid < 128) { s_s1[tid] = 0.f; s_s2[tid] = 0.f; }
    __syncthreads();

    int w = tid >> 5, lane = tid & 31;
    int dst = blockIdx.x * 8 + w;
    int beg = d_rowptr[dst], end = d_rowptr[dst + 1];
    int head = lane >> 3;
    float4 ad = *(const float4*)(d_adst + dst * 4);

    float4 em = make_float4(-1e30f, -1e30f, -1e30f, -1e30f);
    for (int base = beg; base < end; base += 32) {
        int idx = base + lane;
        if (idx < end) {
            int s = d_colsrc[idx];
            float4 a = *(const float4*)(d_asrc + s * 4);
            em.x = fmaxf(em.x, leaky(a.x + ad.x));
            em.y = fmaxf(em.y, leaky(a.y + ad.y));
            em.z = fmaxf(em.z, leaky(a.z + ad.z));
            em.w = fmaxf(em.w, leaky(a.w + ad.w));
        }
    }
#pragma unroll
    for (int d = 16; d; d >>= 1) {
        em.x = fmaxf(em.x, __shfl_xor_sync(0xffffffffu, em.x, d));
        em.y = fmaxf(em.y, __shfl_xor_sync(0xffffffffu, em.y, d));
        em.z = fmaxf(em.z, __shfl_xor_sync(0xffffffffu, em.z, d));
        em.w = fmaxf(em.w, __shfl_xor_sync(0xffffffffu, em.w, d));
    }

    float4 ds  = make_float4(0.f, 0.f, 0.f, 0.f);
    float4 acc = make_float4(0.f, 0.f, 0.f, 0.f);
    for (int base = beg; base < end; base += 32) {
        int idx = base + lane;
        int nE = min(32, end - base);
        if (idx < end) {
            int s = d_colsrc[idx];
            float4 a = *(const float4*)(d_asrc + s * 4);
            float4 wv;
            wv.x = __expf(leaky(a.x + ad.x) - em.x);
            wv.y = __expf(leaky(a.y + ad.y) - em.y);
            wv.z = __expf(leaky(a.z + ad.z) - em.z);
            wv.w = __expf(leaky(a.w + ad.w) - em.w);
            ds.x += wv.x; ds.y += wv.y; ds.z += wv.z; ds.w += wv.w;
            s_src[w][lane] = s;
            *(float4*)&s_w[w][lane * 4] = wv;
        }
        __syncwarp();
        const float* hb = d_hlin + lane * 4;
        int j = 0;
        for (; j + 8 <= nE; j += 8) {
            int   si[8];
            float wi[8];
            float4 hv[8];
#pragma unroll
            for (int u = 0; u < 8; u++) {
                si[u] = s_src[w][j + u];
                wi[u] = s_w[w][(j + u) * 4 + head];
            }
#pragma unroll
            for (int u = 0; u < 8; u++)
                hv[u] = *(const float4*)(hb + (size_t)si[u] * 128);
#pragma unroll
            for (int u = 0; u < 8; u++) {
                acc.x += hv[u].x * wi[u]; acc.y += hv[u].y * wi[u];
                acc.z += hv[u].z * wi[u]; acc.w += hv[u].w * wi[u];
            }
        }
        for (; j < nE; j++) {
            int s = s_src[w][j];
            float wt = s_w[w][j * 4 + head];
            float4 hv = *(const float4*)(hb + (size_t)s * 128);
            acc.x += hv.x * wt; acc.y += hv.y * wt;
            acc.z += hv.z * wt; acc.w += hv.w * wt;
        }
        __syncwarp();
    }
#pragma unroll
    for (int d = 16; d; d >>= 1) {
        ds.x += __shfl_xor_sync(0xffffffffu, ds.x, d);
        ds.y += __shfl_xor_sync(0xffffffffu, ds.y, d);
        ds.z += __shfl_xor_sync(0xffffffffu, ds.z, d);
        ds.w += __shfl_xor_sync(0xffffffffu, ds.w, d);
    }
    float dn = (head == 0) ? ds.x : (head == 1) ? ds.y : (head == 2) ? ds.z : ds.w;
    float inv = 1.0f / dn;
    float4 b4 = *(const float4*)(bias_l + lane * 4);
    float4 o = make_float4(acc.x * inv + b4.x, acc.y * inv + b4.y,
                           acc.z * inv + b4.z, acc.w * inv + b4.w);
    *(float4*)(d_bufG + (size_t)dst * 128 + lane * 4) = o;

    int c0 = lane * 4;
    atomicAdd(&s_s1[c0+0], o.x); atomicAdd(&s_s1[c0+1], o.y);
    atomicAdd(&s_s1[c0+2], o.z); atomicAdd(&s_s1[c0+3], o.w);
    atomicAdd(&s_s2[c0+0], o.x*o.x); atomicAdd(&s_s2[c0+1], o.y*o.y);
    atomicAdd(&s_s2[c0+2], o.z*o.z); atomicAdd(&s_s2[c0+3], o.w*o.w);
    __syncthreads();
    if (tid < 128) {
        atomicAdd(&bnsum[tid], s_s1[tid]);
        atomicAdd(&bnsq[tid],  s_s2[tid]);
    }
}

// ---------------- final BN apply + residual + ReLU (layer 5 only) ----------------
__global__ void k_bn(const float* __restrict__ gamma, const float* __restrict__ beta,
                     const float* __restrict__ bsum,  const float* __restrict__ bsq,
                     const float* __restrict__ skip,  float* __restrict__ out) {
    __shared__ float sc[128], sh[128];
    int tid = threadIdx.x;
    if (tid < 128) {
        float mu  = bsum[tid] * INVN;
        float var = bsq[tid] * INVN - mu * mu;
        float r = rsqrtf(var + 1e-5f);
        float gg = gamma[tid] * r;
        sc[tid] = gg;
        sh[tid] = beta[tid] - gg * mu;
    }
    __syncthreads();
    size_t g4 = (size_t)blockIdx.x * 256 + tid;
    int q = (int)(g4 & 31) * 4;
    float4 v = ((const float4*)d_bufG)[g4];
    float4 y;
    y.x = v.x * sc[q+0] + sh[q+0];
    y.y = v.y * sc[q+1] + sh[q+1];
    y.z = v.z * sc[q+2] + sh[q+2];
    y.w = v.w * sc[q+3] + sh[q+3];
    if (skip) {
        float4 s4 = ((const float4*)skip)[g4];
        y.x += s4.x; y.y += s4.y; y.z += s4.z; y.w += s4.w;
    }
    y.x = fmaxf(y.x, 0.f); y.y = fmaxf(y.y, 0.f);
    y.z = fmaxf(y.z, 0.f); y.w = fmaxf(y.w, 0.f);
    ((float4*)out)[g4] = y;
}

// ---------------- launch ----------------
extern "C" void kernel_launch(void* const* d_in, const int* in_sizes, int n_in,
                              void* d_out, int out_size) {
    const float* x       = (const float*)d_in[0];
    const int*   ei      = (const int*)  d_in[1];
    const float* Ws      = (const float*)d_in[2];
    const float* att_src = (const float*)d_in[3];
    const float* att_dst = (const float*)d_in[4];
    const float* biases  = (const float*)d_in[5];
    const float* gammas  = (const float*)d_in[6];
    const float* betas   = (const float*)d_in[7];
    float* out = (float*)d_out;

    void *pA, *pB, *pG, *pSum, *pSq, *pWh, *pWl;
    cudaGetSymbolAddress(&pA, d_bufA);
    cudaGetSymbolAddress(&pB, d_bufB);
    cudaGetSymbolAddress(&pG, d_bufG);
    cudaGetSymbolAddress(&pSum, d_bnsum);
    cudaGetSymbolAddress(&pSq,  d_bnsq);
    cudaGetSymbolAddress(&pWh,  d_whi);
    cudaGetSymbolAddress(&pWl,  d_wlo);
    float* A = (float*)pA;
    float* B = (float*)pB;
    float* G = (float*)pG;
    float* bnsum = (float*)pSum;
    float* bnsq  = (float*)pSq;
    float* whi   = (float*)pWh;
    float* wlo   = (float*)pWl;

    cudaFuncSetAttribute(k_gemm_tc, cudaFuncAttributeMaxDynamicSharedMemorySize, GSM_BYTES);

    // launch index 3 = layer-0 GEMM (ncu profiles index 3)
    k_init<<<384, 256>>>(Ws);                                    // 0
    k_count<<<(ETOT + 255) / 256, 256>>>(ei);                    // 1
    k_scan_reduce<<<NBLK_SCAN, 256>>>();                         // 2
    k_gemm_tc<<<GEMM_CTAS, 256, GSM_BYTES>>>(x, whi, wlo,        // 3  <- profiled
                                             att_src, att_dst,
                                             0, 0, 0, 0, 0, 0);
    k_scan_write<<<NBLK_SCAN, 256>>>();                          // 4
    k_scatter<<<(ETOT + 255) / 256, 256>>>(ei);                  // 5
    k_agg<<<NN / 8, 256>>>(biases, bnsum, bnsq);                 // 6 (layer 0)

    // layers 1..5: GEMM fuses BN/ReLU/skip of layer l-1
    for (int l = 1; l < NL; l++) {
        const float* skip  = (l == 4) ? B : 0;   // y3 = relu(bn3(G) + y1)
        float*       wrY   = (l == 2) ? B :      // materialize y1
                             (l == 4) ? A : 0;   // materialize y3
        k_gemm_tc<<<GEMM_CTAS, 256, GSM_BYTES>>>(G,
                                                 whi + (size_t)l * 16384,
                                                 wlo + (size_t)l * 16384,
                                                 att_src + l * 128, att_dst + l * 128,
                                                 bnsum + (l - 1) * 128, bnsq + (l - 1) * 128,
                                                 gammas + (l - 1) * 128, betas + (l - 1) * 128,
                                                 skip, wrY);
        k_agg<<<NN / 8, 256>>>(biases + l * 128, bnsum + l * 128, bnsq + l * 128);
    }

    // final output: y5 = relu(bn5(G) + y3)
    k_bn<<<NN / 8, 256>>>(gammas + 5 * 128, betas + 5 * 128,
                          bnsum + 5 * 128, bnsq + 5 * 128, A, out);
}

// round 5
// speedup vs baseline: 1.1085x; 1.1085x over previous
#include <cuda_runtime.h>
#include <cstdint>

#define NN   50000
#define NE   600000
#define ETOT 650000          // NE + NN self loops
#define CH   128
#define NL   6
#define NEG  0.2f
#define INVN (1.0f/50000.0f)
#define NBLK_SCAN 196        // ceil(50000/256)
#define GEMM_CTAS 391        // ceil(50000/128)
#define WTOT (NL*128*128)    // 98304

// ---------------- scratch (static __device__ arrays, no allocation) ----------------
__device__ float d_bufA[(size_t)NN*CH];   // holds y3 residual
__device__ float d_bufB[(size_t)NN*CH];   // holds y1 residual
__device__ float d_bufG[(size_t)NN*CH];   // pre-BN GAT output of current layer
__device__ float d_hlin[(size_t)NN*CH];
__device__ float d_asrc[NN*4];
__device__ float d_adst[NN*4];
__device__ int   d_deg[NN];
__device__ int   d_rowptr[NN+1];
__device__ int   d_colsrc[ETOT];
__device__ int   d_bsums[256];
__device__ float d_bnsum[NL*CH];
__device__ float d_bnsq[NL*CH];
// W split into tf32 hi/lo, pre-reordered into the GEMM smem image layout
__device__ float d_whi[WTOT];
__device__ float d_wlo[WTOT];

// ---------------- helpers ----------------
__device__ __forceinline__ float leaky(float x) {
    return fmaxf(x, 0.f) + NEG * fminf(x, 0.f);
}
__device__ __forceinline__ uint32_t f2tf32(float x) {
    uint32_t r;
    asm("cvt.rna.tf32.f32 %0, %1;" : "=r"(r) : "f"(x));
    return r;
}
__device__ __forceinline__ void mma8(float* c, uint32_t a0, uint32_t a1,
                                     uint32_t a2, uint32_t a3,
                                     uint32_t b0, uint32_t b1) {
    asm volatile(
        "mma.sync.aligned.m16n8k8.row.col.f32.tf32.tf32.f32 "
        "{%0,%1,%2,%3}, {%4,%5,%6,%7}, {%8,%9}, {%0,%1,%2,%3};"
        : "+f"(c[0]), "+f"(c[1]), "+f"(c[2]), "+f"(c[3])
        : "r"(a0), "r"(a1), "r"(a2), "r"(a3), "r"(b0), "r"(b1));
}

// ---------------- init: zero counters + split/reorder W (once) ----------------
__global__ void k_init(const float* __restrict__ Ws) {
    int i = blockIdx.x * 256 + threadIdx.x;     // grid 384 -> 98304 threads
    if (i < NN) d_deg[i] = 0;
    if (i < NL*CH) { d_bnsum[i] = 0.f; d_bnsq[i] = 0.f; }
    if (i == 0) d_rowptr[NN] = ETOT;
    if (i < WTOT) {
        int l = i >> 14, rem = i & 16383;
        int k = rem >> 7, n = rem & 127;
        float v = Ws[i];
        uint32_t hb = f2tf32(v);
        uint32_t lb = f2tf32(v - __uint_as_float(hb));
        int pos = l * 16384 + n * 128 + ((k >> 5) << 5)
                + (((k >> 3) & 3) << 3) + ((k & 3) << 1) + ((k >> 2) & 1);
        d_whi[pos] = __uint_as_float(hb);
        d_wlo[pos] = __uint_as_float(lb);
    }
}

// ---------------- CSR build (by destination) ----------------
__global__ void k_count(const int* __restrict__ ei) {
    int e = blockIdx.x * blockDim.x + threadIdx.x;
    if (e >= ETOT) return;
    int dst = (e < NE) ? ei[NE + e] : (e - NE);
    atomicAdd(&d_deg[dst], 1);
}

__global__ void k_scan_reduce() {
    __shared__ int s[256];
    int i = blockIdx.x * 256 + threadIdx.x;
    s[threadIdx.x] = (i < NN) ? d_deg[i] : 0;
    __syncthreads();
    for (int off = 128; off; off >>= 1) {
        if (threadIdx.x < off) s[threadIdx.x] += s[threadIdx.x + off];
        __syncthreads();
    }
    if (threadIdx.x == 0) d_bsums[blockIdx.x] = s[0];
}

__global__ void k_scan_write() {
    __shared__ int s[256];
    __shared__ int soff[256];
    int tid = threadIdx.x;
    int i = blockIdx.x * 256 + tid;
    int v = (i < NN) ? d_deg[i] : 0;
    soff[tid] = (tid < blockIdx.x) ? d_bsums[tid] : 0;
    s[tid] = v;
    __syncthreads();
    for (int off = 128; off; off >>= 1) {
        if (tid < off) soff[tid] += soff[tid + off];
        __syncthreads();
    }
    for (int off = 1; off < 256; off <<= 1) {
        int t = (tid >= off) ? s[tid - off] : 0;
        __syncthreads();
        s[tid] += t;
        __syncthreads();
    }
    if (i < NN) {
        d_rowptr[i] = soff[0] + s[tid] - v;
        d_deg[i] = 0;
    }
}

__global__ void k_scatter(const int* __restrict__ ei) {
    int e = blockIdx.x * blockDim.x + threadIdx.x;
    if (e >= ETOT) return;
    int src, dst;
    if (e < NE) { src = ei[e]; dst = ei[NE + e]; }
    else        { src = dst = e - NE; }
    int pos = d_rowptr[dst] + atomicAdd(&d_deg[dst], 1);
    d_colsrc[pos] = src;
}

// ---------------- tensor-core GEMM (mma.sync tf32, 3-term), 512 threads ----------------
// 16 warps, warp grid 4(M)x4(N), warp tile 32x32; tile M=128 N=128.
// Double-buffered smem chunks + register prefetch (1 sync per chunk).
// smem floats per buf: Ahi 5120 | Alo 5120 | Bhi 5120 | Blo 5120 = 20480
// bufs at 0 and 20480; attS 40960, attD 41088, sc 41216, sh 41344 -> 41472 floats
#define GSM_BYTES  165888

__global__ void __launch_bounds__(512, 1)
k_gemm_tc(const float* __restrict__ Ain, const float* __restrict__ Whi,
          const float* __restrict__ Wlo,
          const float* __restrict__ attS, const float* __restrict__ attD,
          const float* __restrict__ bsum, const float* __restrict__ bsq,
          const float* __restrict__ gamma, const float* __restrict__ beta,
          const float* __restrict__ skip, float* __restrict__ writeY) {
    extern __shared__ float smf[];
    float* sAt = smf + 40960;
    float* dAt = smf + 41088;
    float* sc  = smf + 41216;
    float* sh  = smf + 41344;

    int tid = threadIdx.x;
    int lane = tid & 31, g = lane >> 2, t = lane & 3;
    int w = tid >> 5, wm = w >> 2, wn = w & 3;
    int bm = blockIdx.x * 128;

    if (tid < 128) sAt[tid] = attS[tid];
    else if (tid < 256) dAt[tid - 128] = attD[tid - 128];
    else if (bsum != 0 && tid < 384) {
        int c = tid - 256;
        float mu  = bsum[c] * INVN;
        float var = bsq[c] * INVN - mu * mu;
        float r = rsqrtf(var + 1e-5f);
        float gg = gamma[c] * r;
        sc[c] = gg;
        sh[c] = beta[c] - gg * mu;
    }

    float cfr[2][4][4];
#pragma unroll
    for (int i = 0; i < 2; i++)
#pragma unroll
        for (int j = 0; j < 4; j++)
#pragma unroll
            for (int q = 0; q < 4; q++) cfr[i][j][q] = 0.f;

    // staging indices (constant per thread across chunks)
    int aF0  = tid,        aF1  = tid + 512;        // A float4 slots
    int aRow0 = aF0 >> 3,  aJ0 = aF0 & 7;
    int aRow1 = aF1 >> 3,  aJ1 = aF1 & 7;
    int gr0 = bm + aRow0,  gr1 = bm + aRow1;

    float4 aPre[2], sPre[2], bhP[2], blP[2];

    // ---- prefetch chunk 0 ----
    {
        const int kc = 0;
        aPre[0] = make_float4(0.f,0.f,0.f,0.f);
        aPre[1] = make_float4(0.f,0.f,0.f,0.f);
        if (gr0 < NN) aPre[0] = *(const float4*)(Ain + (size_t)gr0*128 + kc*32 + aJ0*4);
        if (gr1 < NN) aPre[1] = *(const float4*)(Ain + (size_t)gr1*128 + kc*32 + aJ1*4);
        if (skip) {
            if (gr0 < NN) sPre[0] = *(const float4*)(skip + (size_t)gr0*128 + kc*32 + aJ0*4);
            if (gr1 < NN) sPre[1] = *(const float4*)(skip + (size_t)gr1*128 + kc*32 + aJ1*4);
        }
#pragma unroll
        for (int it = 0; it < 2; it++) {
            int f = tid + it*512, n = f >> 3, q = f & 7;
            int gi = n*32 + kc*8 + q;
            bhP[it] = ((const float4*)Whi)[gi];
            blP[it] = ((const float4*)Wlo)[gi];
        }
    }
    __syncthreads();   // att/sc/sh ready

    for (int kc = 0; kc < 4; kc++) {
        float* base = smf + (kc & 1) * 20480;
        // ---- STS A (transform + tf32 split) ----
#pragma unroll
        for (int it = 0; it < 2; it++) {
            int row = it ? aRow1 : aRow0;
            int j   = it ? aJ1   : aJ0;
            int gr  = it ? gr1   : gr0;
            float4 v = aPre[it];
            if (bsum != 0 && gr < NN) {
                int ch = kc*32 + j*4;
                v.x = v.x * sc[ch+0] + sh[ch+0];
                v.y = v.y * sc[ch+1] + sh[ch+1];
                v.z = v.z * sc[ch+2] + sh[ch+2];
                v.w = v.w * sc[ch+3] + sh[ch+3];
                if (skip) {
                    v.x += sPre[it].x; v.y += sPre[it].y;
                    v.z += sPre[it].z; v.w += sPre[it].w;
                }
                v.x = fmaxf(v.x, 0.f); v.y = fmaxf(v.y, 0.f);
                v.z = fmaxf(v.z, 0.f); v.w = fmaxf(v.w, 0.f);
                if (writeY)
                    *(float4*)(writeY + (size_t)gr*128 + kc*32 + j*4) = v;
            }
            int ks = j >> 1, half = j & 1;
            float* ph = base + row*40 + ks*8 + half;
            float* pl = ph + 5120;
            float vv[4] = {v.x, v.y, v.z, v.w};
#pragma unroll
            for (int cc = 0; cc < 4; cc++) {
                uint32_t hb = f2tf32(vv[cc]);
                ph[cc*2] = __uint_as_float(hb);
                pl[cc*2] = __uint_as_float(f2tf32(vv[cc] - __uint_as_float(hb)));
            }
        }
        // ---- STS B ----
#pragma unroll
        for (int it = 0; it < 2; it++) {
            int f = tid + it*512, n = f >> 3, q = f & 7;
            *(float4*)(base + 10240 + n*40 + q*4) = bhP[it];
            *(float4*)(base + 15360 + n*40 + q*4) = blP[it];
        }
        __syncthreads();

        // ---- prefetch next chunk (overlaps with compute below) ----
        if (kc < 3) {
            int kn = kc + 1;
            aPre[0] = make_float4(0.f,0.f,0.f,0.f);
            aPre[1] = make_float4(0.f,0.f,0.f,0.f);
            if (gr0 < NN) aPre[0] = *(const float4*)(Ain + (size_t)gr0*128 + kn*32 + aJ0*4);
            if (gr1 < NN) aPre[1] = *(const float4*)(Ain + (size_t)gr1*128 + kn*32 + aJ1*4);
            if (skip) {
                if (gr0 < NN) sPre[0] = *(const float4*)(skip + (size_t)gr0*128 + kn*32 + aJ0*4);
                if (gr1 < NN) sPre[1] = *(const float4*)(skip + (size_t)gr1*128 + kn*32 + aJ1*4);
            }
#pragma unroll
            for (int it = 0; it < 2; it++) {
                int f = tid + it*512, n = f >> 3, q = f & 7;
                int gi = n*32 + kn*8 + q;
                bhP[it] = ((const float4*)Whi)[gi];
                blP[it] = ((const float4*)Wlo)[gi];
            }
        }

        // ---- compute 4 ksteps on this buffer ----
        float2* A2h = (float2*)base;
        float2* A2l = (float2*)(base + 5120);
        float2* B2h = (float2*)(base + 10240);
        float2* B2l = (float2*)(base + 15360);
#pragma unroll
        for (int ks = 0; ks < 4; ks++) {
            float2 ah[2][2], al[2][2];
#pragma unroll
            for (int mt = 0; mt < 2; mt++) {
                int r0 = wm*32 + mt*16 + g;
                ah[mt][0] = A2h[r0*20 + ks*4 + t];
                ah[mt][1] = A2h[(r0+8)*20 + ks*4 + t];
                al[mt][0] = A2l[r0*20 + ks*4 + t];
                al[mt][1] = A2l[(r0+8)*20 + ks*4 + t];
            }
#pragma unroll
            for (int nt = 0; nt < 4; nt++) {
                int n = wn*32 + nt*8 + g;
                float2 bh = B2h[n*20 + ks*4 + t];
                float2 bl = B2l[n*20 + ks*4 + t];
                uint32_t bh0 = __float_as_uint(bh.x), bh1 = __float_as_uint(bh.y);
                uint32_t bl0 = __float_as_uint(bl.x), bl1 = __float_as_uint(bl.y);
#pragma unroll
                for (int mt = 0; mt < 2; mt++) {
                    uint32_t a0 = __float_as_uint(ah[mt][0].x);
                    uint32_t a1 = __float_as_uint(ah[mt][1].x);
                    uint32_t a2 = __float_as_uint(ah[mt][0].y);
                    uint32_t a3 = __float_as_uint(ah[mt][1].y);
                    mma8(cfr[mt][nt], a0, a1, a2, a3, bh0, bh1);   // hi*hi
                    mma8(cfr[mt][nt], a0, a1, a2, a3, bl0, bl1);   // hi*lo
                    uint32_t l0 = __float_as_uint(al[mt][0].x);
                    uint32_t l1 = __float_as_uint(al[mt][1].x);
                    uint32_t l2 = __float_as_uint(al[mt][0].y);
                    uint32_t l3 = __float_as_uint(al[mt][1].y);
                    mma8(cfr[mt][nt], l0, l1, l2, l3, bh0, bh1);   // lo*hi
                }
            }
        }
        // no trailing sync: next iteration's STS targets the other buffer; its
        // sync orders all warps' compute(kc) (program-order before STS kc+1)
    }

    // ---- epilogue: store h + fused per-head alpha dots (head == wn) ----
#pragma unroll
    for (int mt = 0; mt < 2; mt++) {
#pragma unroll
        for (int rr = 0; rr < 2; rr++) {
            int row = bm + wm*32 + mt*16 + rr*8 + g;
            float ps = 0.f, pd = 0.f;
#pragma unroll
            for (int nt = 0; nt < 4; nt++) {
                float c0 = cfr[mt][nt][rr*2 + 0];
                float c1 = cfr[mt][nt][rr*2 + 1];
                int col0 = wn*32 + nt*8 + 2*t;
                if (row < NN)
                    *(float2*)(d_hlin + (size_t)row*128 + col0) = make_float2(c0, c1);
                ps += c0 * sAt[col0] + c1 * sAt[col0 + 1];
                pd += c0 * dAt[col0] + c1 * dAt[col0 + 1];
            }
            ps += __shfl_down_sync(0xffffffffu, ps, 2, 4);
            ps += __shfl_down_sync(0xffffffffu, ps, 1, 4);
            pd += __shfl_down_sync(0xffffffffu, pd, 2, 4);
            pd += __shfl_down_sync(0xffffffffu, pd, 1, 4);
            if (t == 0 && row < NN) {
                d_asrc[row*4 + wn] = ps;
                d_adst[row*4 + wn] = pd;
            }
        }
    }
}

// ---------------- GAT aggregation (warp per dst) + BN stats ----------------
__global__ void k_agg(const float* __restrict__ bias_l,
                      float* __restrict__ bnsum, float* __restrict__ bnsq) {
    __shared__ int   s_src[8][32];
    __shared__ float s_w[8][128];
    __shared__ float s_s1[128], s_s2[128];
    int tid = threadIdx.x;
    if (tid < 128) { s_s1[tid] = 0.f; s_s2[tid] = 0.f; }
    __syncthreads();

    int w = tid >> 5, lane = tid & 31;
    int dst = blockIdx.x * 8 + w;
    int beg = d_rowptr[dst], end = d_rowptr[dst + 1];
    int head = lane >> 3;
    float4 ad = *(const float4*)(d_adst + dst * 4);

    float4 em = make_float4(-1e30f, -1e30f, -1e30f, -1e30f);
    for (int base = beg; base < end; base += 32) {
        int idx = base + lane;
        if (idx < end) {
            int s = d_colsrc[idx];
            float4 a = *(const float4*)(d_asrc + s * 4);
            em.x = fmaxf(em.x, leaky(a.x + ad.x));
            em.y = fmaxf(em.y, leaky(a.y + ad.y));
            em.z = fmaxf(em.z, leaky(a.z + ad.z));
            em.w = fmaxf(em.w, leaky(a.w + ad.w));
        }
    }
#pragma unroll
    for (int d = 16; d; d >>= 1) {
        em.x = fmaxf(em.x, __shfl_xor_sync(0xffffffffu, em.x, d));
        em.y = fmaxf(em.y, __shfl_xor_sync(0xffffffffu, em.y, d));
        em.z = fmaxf(em.z, __shfl_xor_sync(0xffffffffu, em.z, d));
        em.w = fmaxf(em.w, __shfl_xor_sync(0xffffffffu, em.w, d));
    }

    float4 ds  = make_float4(0.f, 0.f, 0.f, 0.f);
    float4 acc = make_float4(0.f, 0.f, 0.f, 0.f);
    for (int base = beg; base < end; base += 32) {
        int idx = base + lane;
        int nE = min(32, end - base);
        if (idx < end) {
            int s = d_colsrc[idx];
            float4 a = *(const float4*)(d_asrc + s * 4);
            float4 wv;
            wv.x = __expf(leaky(a.x + ad.x) - em.x);
            wv.y = __expf(leaky(a.y + ad.y) - em.y);
            wv.z = __expf(leaky(a.z + ad.z) - em.z);
            wv.w = __expf(leaky(a.w + ad.w) - em.w);
            ds.x += wv.x; ds.y += wv.y; ds.z += wv.z; ds.w += wv.w;
            s_src[w][lane] = s;
            *(float4*)&s_w[w][lane * 4] = wv;
        }
        __syncwarp();
        const float* hb = d_hlin + lane * 4;
        int j = 0;
        for (; j + 8 <= nE; j += 8) {
            int   si[8];
            float wi[8];
            float4 hv[8];
#pragma unroll
            for (int u = 0; u < 8; u++) {
                si[u] = s_src[w][j + u];
                wi[u] = s_w[w][(j + u) * 4 + head];
            }
#pragma unroll
            for (int u = 0; u < 8; u++)
                hv[u] = *(const float4*)(hb + (size_t)si[u] * 128);
#pragma unroll
            for (int u = 0; u < 8; u++) {
                acc.x += hv[u].x * wi[u]; acc.y += hv[u].y * wi[u];
                acc.z += hv[u].z * wi[u]; acc.w += hv[u].w * wi[u];
            }
        }
        for (; j < nE; j++) {
            int s = s_src[w][j];
            float wt = s_w[w][j * 4 + head];
            float4 hv = *(const float4*)(hb + (size_t)s * 128);
            acc.x += hv.x * wt; acc.y += hv.y * wt;
            acc.z += hv.z * wt; acc.w += hv.w * wt;
        }
        __syncwarp();
    }
#pragma unroll
    for (int d = 16; d; d >>= 1) {
        ds.x += __shfl_xor_sync(0xffffffffu, ds.x, d);
        ds.y += __shfl_xor_sync(0xffffffffu, ds.y, d);
        ds.z += __shfl_xor_sync(0xffffffffu, ds.z, d);
        ds.w += __shfl_xor_sync(0xffffffffu, ds.w, d);
    }
    float dn = (head == 0) ? ds.x : (head == 1) ? ds.y : (head == 2) ? ds.z : ds.w;
    float inv = 1.0f / dn;
    float4 b4 = *(const float4*)(bias_l + lane * 4);
    float4 o = make_float4(acc.x * inv + b4.x, acc.y * inv + b4.y,
                           acc.z * inv + b4.z, acc.w * inv + b4.w);
    *(float4*)(d_bufG + (size_t)dst * 128 + lane * 4) = o;

    int c0 = lane * 4;
    atomicAdd(&s_s1[c0+0], o.x); atomicAdd(&s_s1[c0+1], o.y);
    atomicAdd(&s_s1[c0+2], o.z); atomicAdd(&s_s1[c0+3], o.w);
    atomicAdd(&s_s2[c0+0], o.x*o.x); atomicAdd(&s_s2[c0+1], o.y*o.y);
    atomicAdd(&s_s2[c0+2], o.z*o.z); atomicAdd(&s_s2[c0+3], o.w*o.w);
    __syncthreads();
    if (tid < 128) {
        atomicAdd(&bnsum[tid], s_s1[tid]);
        atomicAdd(&bnsq[tid],  s_s2[tid]);
    }
}

// ---------------- final BN apply + residual + ReLU (layer 5 only) ----------------
__global__ void k_bn(const float* __restrict__ gamma, const float* __restrict__ beta,
                     const float* __restrict__ bsum,  const float* __restrict__ bsq,
                     const float* __restrict__ skip,  float* __restrict__ out) {
    __shared__ float sc[128], sh[128];
    int tid = threadIdx.x;
    if (tid < 128) {
        float mu  = bsum[tid] * INVN;
        float var = bsq[tid] * INVN - mu * mu;
        float r = rsqrtf(var + 1e-5f);
        float gg = gamma[tid] * r;
        sc[tid] = gg;
        sh[tid] = beta[tid] - gg * mu;
    }
    __syncthreads();
    size_t g4 = (size_t)blockIdx.x * 256 + tid;
    int q = (int)(g4 & 31) * 4;
    float4 v = ((const float4*)d_bufG)[g4];
    float4 y;
    y.x = v.x * sc[q+0] + sh[q+0];
    y.y = v.y * sc[q+1] + sh[q+1];
    y.z = v.z * sc[q+2] + sh[q+2];
    y.w = v.w * sc[q+3] + sh[q+3];
    if (skip) {
        float4 s4 = ((const float4*)skip)[g4];
        y.x += s4.x; y.y += s4.y; y.z += s4.z; y.w += s4.w;
    }
    y.x = fmaxf(y.x, 0.f); y.y = fmaxf(y.y, 0.f);
    y.z = fmaxf(y.z, 0.f); y.w = fmaxf(y.w, 0.f);
    ((float4*)out)[g4] = y;
}

// ---------------- launch ----------------
extern "C" void kernel_launch(void* const* d_in, const int* in_sizes, int n_in,
                              void* d_out, int out_size) {
    const float* x       = (const float*)d_in[0];
    const int*   ei      = (const int*)  d_in[1];
    const float* Ws      = (const float*)d_in[2];
    const float* att_src = (const float*)d_in[3];
    const float* att_dst = (const float*)d_in[4];
    const float* biases  = (const float*)d_in[5];
    const float* gammas  = (const float*)d_in[6];
    const float* betas   = (const float*)d_in[7];
    float* out = (float*)d_out;

    void *pA, *pB, *pG, *pSum, *pSq, *pWh, *pWl;
    cudaGetSymbolAddress(&pA, d_bufA);
    cudaGetSymbolAddress(&pB, d_bufB);
    cudaGetSymbolAddress(&pG, d_bufG);
    cudaGetSymbolAddress(&pSum, d_bnsum);
    cudaGetSymbolAddress(&pSq,  d_bnsq);
    cudaGetSymbolAddress(&pWh,  d_whi);
    cudaGetSymbolAddress(&pWl,  d_wlo);
    float* A = (float*)pA;
    float* B = (float*)pB;
    float* G = (float*)pG;
    float* bnsum = (float*)pSum;
    float* bnsq  = (float*)pSq;
    float* whi   = (float*)pWh;
    float* wlo   = (float*)pWl;

    cudaFuncSetAttribute(k_gemm_tc, cudaFuncAttributeMaxDynamicSharedMemorySize, GSM_BYTES);

    // launch index 3 = layer-0 GEMM (ncu profiles index 3)
    k_init<<<384, 256>>>(Ws);                                    // 0
    k_count<<<(ETOT + 255) / 256, 256>>>(ei);                    // 1
    k_scan_reduce<<<NBLK_SCAN, 256>>>();                         // 2
    k_gemm_tc<<<GEMM_CTAS, 512, GSM_BYTES>>>(x, whi, wlo,        // 3  <- profiled
                                             att_src, att_dst,
                                             0, 0, 0, 0, 0, 0);
    k_scan_write<<<NBLK_SCAN, 256>>>();                          // 4
    k_scatter<<<(ETOT + 255) / 256, 256>>>(ei);                  // 5
    k_agg<<<NN / 8, 256>>>(biases, bnsum, bnsq);                 // 6 (layer 0)

    // layers 1..5: GEMM fuses BN/ReLU/skip of layer l-1
    for (int l = 1; l < NL; l++) {
        const float* skip  = (l == 4) ? B : 0;   // y3 = relu(bn3(G) + y1)
        float*       wrY   = (l == 2) ? B :      // materialize y1
                             (l == 4) ? A : 0;   // materialize y3
        k_gemm_tc<<<GEMM_CTAS, 512, GSM_BYTES>>>(G,
                                                 whi + (size_t)l * 16384,
                                                 wlo + (size_t)l * 16384,
                                                 att_src + l * 128, att_dst + l * 128,
                                                 bnsum + (l - 1) * 128, bnsq + (l - 1) * 128,
                                                 gammas + (l - 1) * 128, betas + (l - 1) * 128,
                                                 skip, wrY);
        k_agg<<<NN / 8, 256>>>(biases + l * 128, bnsum + l * 128, bnsq + l * 128);
    }

    // final output: y5 = relu(bn5(G) + y3)
    k_bn<<<NN / 8, 256>>>(gammas + 5 * 128, betas + 5 * 128,
                          bnsum + 5 * 128, bnsq + 5 * 128, A, out);
}

// round 7
// speedup vs baseline: 1.1378x; 1.0264x over previous
#include <cuda_runtime.h>
#include <cstdint>

#define NN   50000
#define NE   600000
#define ETOT 650000          // NE + NN self loops
#define CH   128
#define NL   6
#define NEG  0.2f
#define INVN (1.0f/50000.0f)
#define NBLK_SCAN 196        // ceil(50000/256)
#define GEMM_CTAS 391        // ceil(50000/128)
#define WTOT (NL*128*128)    // 98304

// ---------------- scratch (static __device__ arrays, no allocation) ----------------
__device__ float d_bufA[(size_t)NN*CH];   // holds y3 residual
__device__ float d_bufB[(size_t)NN*CH];   // holds y1 residual
__device__ float d_bufG[(size_t)NN*CH];   // pre-BN GAT output of current layer
__device__ float d_hlin[(size_t)NN*CH];
__device__ float d_asrc[NN*4];
__device__ float d_adst[NN*4];
__device__ int   d_deg[NN];
__device__ int   d_rowptr[NN+1];
__device__ int   d_colsrc[ETOT];
__device__ int   d_bsums[256];
__device__ float d_bnsum[NL*CH];
__device__ float d_bnsq[NL*CH];
// W split into tf32 hi/lo, pre-reordered into the GEMM smem image layout
__device__ float d_whi[WTOT];
__device__ float d_wlo[WTOT];

// ---------------- helpers ----------------
__device__ __forceinline__ float leaky(float x) {
    return fmaxf(x, 0.f) + NEG * fminf(x, 0.f);
}
__device__ __forceinline__ uint32_t f2tf32(float x) {
    uint32_t r;
    asm("cvt.rna.tf32.f32 %0, %1;" : "=r"(r) : "f"(x));
    return r;
}
__device__ __forceinline__ void mma8(float* c, uint32_t a0, uint32_t a1,
                                     uint32_t a2, uint32_t a3,
                                     uint32_t b0, uint32_t b1) {
    asm volatile(
        "mma.sync.aligned.m16n8k8.row.col.f32.tf32.tf32.f32 "
        "{%0,%1,%2,%3}, {%4,%5,%6,%7}, {%8,%9}, {%0,%1,%2,%3};"
        : "+f"(c[0]), "+f"(c[1]), "+f"(c[2]), "+f"(c[3])
        : "r"(a0), "r"(a1), "r"(a2), "r"(a3), "r"(b0), "r"(b1));
}

// ---------------- init: zero counters + split/reorder W (once) ----------------
__global__ void k_init(const float* __restrict__ Ws) {
    int i = blockIdx.x * 256 + threadIdx.x;     // grid 384 -> 98304 threads
    if (i < NN) d_deg[i] = 0;
    if (i < NL*CH) { d_bnsum[i] = 0.f; d_bnsq[i] = 0.f; }
    if (i == 0) d_rowptr[NN] = ETOT;
    if (i < WTOT) {
        int l = i >> 14, rem = i & 16383;
        int k = rem >> 7, n = rem & 127;
        float v = Ws[i];
        uint32_t hb = f2tf32(v);
        uint32_t lb = f2tf32(v - __uint_as_float(hb));
        int pos = l * 16384 + n * 128 + ((k >> 5) << 5)
                + (((k >> 3) & 3) << 3) + ((k & 3) << 1) + ((k >> 2) & 1);
        d_whi[pos] = __uint_as_float(hb);
        d_wlo[pos] = __uint_as_float(lb);
    }
}

// ---------------- CSR build (by destination) ----------------
__global__ void k_count(const int* __restrict__ ei) {
    int e = blockIdx.x * blockDim.x + threadIdx.x;
    if (e >= ETOT) return;
    int dst = (e < NE) ? ei[NE + e] : (e - NE);
    atomicAdd(&d_deg[dst], 1);
}

__global__ void k_scan_reduce() {
    __shared__ int s[256];
    int i = blockIdx.x * 256 + threadIdx.x;
    s[threadIdx.x] = (i < NN) ? d_deg[i] : 0;
    __syncthreads();
    for (int off = 128; off; off >>= 1) {
        if (threadIdx.x < off) s[threadIdx.x] += s[threadIdx.x + off];
        __syncthreads();
    }
    if (threadIdx.x == 0) d_bsums[blockIdx.x] = s[0];
}

__global__ void k_scan_write() {
    __shared__ int s[256];
    __shared__ int soff[256];
    int tid = threadIdx.x;
    int i = blockIdx.x * 256 + tid;
    int v = (i < NN) ? d_deg[i] : 0;
    soff[tid] = (tid < blockIdx.x) ? d_bsums[tid] : 0;
    s[tid] = v;
    __syncthreads();
    for (int off = 128; off; off >>= 1) {
        if (tid < off) soff[tid] += soff[tid + off];
        __syncthreads();
    }
    for (int off = 1; off < 256; off <<= 1) {
        int t = (tid >= off) ? s[tid - off] : 0;
        __syncthreads();
        s[tid] += t;
        __syncthreads();
    }
    if (i < NN) {
        d_rowptr[i] = soff[0] + s[tid] - v;
        d_deg[i] = 0;
    }
}

__global__ void k_scatter(const int* __restrict__ ei) {
    int e = blockIdx.x * blockDim.x + threadIdx.x;
    if (e >= ETOT) return;
    int src, dst;
    if (e < NE) { src = ei[e]; dst = ei[NE + e]; }
    else        { src = dst = e - NE; }
    int pos = d_rowptr[dst] + atomicAdd(&d_deg[dst], 1);
    d_colsrc[pos] = src;
}

// ---------------- tensor-core GEMM (mma.sync tf32, 3-term), 512 threads ----------------
// 16 warps, warp grid 4(M)x4(N), warp tile 32x32; tile M=128 N=128.
// Double-buffered smem + register prefetch; A staging = vector STS (no scatter).
// smem floats per buf: Ahi 5120 | Alo 5120 | Bhi 5120 | Blo 5120 = 20480
// bufs at 0 and 20480; attS 40960, attD 41088, sc 41216, sh 41344 -> 41472 floats
#define GSM_BYTES  165888

__global__ void __launch_bounds__(512, 1)
k_gemm_tc(const float* __restrict__ Ain, const float* __restrict__ Whi,
          const float* __restrict__ Wlo,
          const float* __restrict__ attS, const float* __restrict__ attD,
          const float* __restrict__ bsum, const float* __restrict__ bsq,
          const float* __restrict__ gamma, const float* __restrict__ beta,
          const float* __restrict__ skip, float* __restrict__ writeY) {
    extern __shared__ float smf[];
    float* sAt = smf + 40960;
    float* dAt = smf + 41088;
    float* sc  = smf + 41216;
    float* sh  = smf + 41344;

    int tid = threadIdx.x;
    int lane = tid & 31, g = lane >> 2, t = lane & 3;
    int w = tid >> 5, wm = w >> 2, wn = w & 3;
    int bm = blockIdx.x * 128;

    if (tid < 128) sAt[tid] = attS[tid];
    else if (tid < 256) dAt[tid - 128] = attD[tid - 128];
    else if (bsum != 0 && tid < 384) {
        int c = tid - 256;
        float mu  = bsum[c] * INVN;
        float var = bsq[c] * INVN - mu * mu;
        float r = rsqrtf(var + 1e-5f);
        float gg = gamma[c] * r;
        sc[c] = gg;
        sh[c] = beta[c] - gg * mu;
    }

    float cfr[2][4][4];
#pragma unroll
    for (int i = 0; i < 2; i++)
#pragma unroll
        for (int j = 0; j < 4; j++)
#pragma unroll
            for (int q = 0; q < 4; q++) cfr[i][j][q] = 0.f;

    // A staging: thread owns one 8-float kstep row. 128 rows x 4 ksteps = 512.
    int sRow = tid >> 2, sKs = tid & 3;
    int sGr  = bm + sRow;
    size_t aBase = (size_t)sGr * 128 + sKs * 8;

    float4 aPre[2], sPre[2], bhP[2], blP[2];

    // ---- prefetch chunk 0 ----
    {
        aPre[0] = make_float4(0.f,0.f,0.f,0.f);
        aPre[1] = make_float4(0.f,0.f,0.f,0.f);
        if (sGr < NN) {
            aPre[0] = *(const float4*)(Ain + aBase);
            aPre[1] = *(const float4*)(Ain + aBase + 4);
            if (skip) {
                sPre[0] = *(const float4*)(skip + aBase);
                sPre[1] = *(const float4*)(skip + aBase + 4);
            }
        }
#pragma unroll
        for (int it = 0; it < 2; it++) {
            int f = tid + it*512, n = f >> 3, q = f & 7;
            int gi = n*32 + q;
            bhP[it] = ((const float4*)Whi)[gi];
            blP[it] = ((const float4*)Wlo)[gi];
        }
    }
    __syncthreads();   // att/sc/sh ready

    for (int kc = 0; kc < 4; kc++) {
        float* base = smf + (kc & 1) * 20480;
        // ---- STS A: BN/ReLU/skip + tf32 split + (k,k+4) interleave in regs ----
        {
            float v[8] = {aPre[0].x, aPre[0].y, aPre[0].z, aPre[0].w,
                          aPre[1].x, aPre[1].y, aPre[1].z, aPre[1].w};
            if (bsum != 0 && sGr < NN) {
                int ch = kc*32 + sKs*8;
#pragma unroll
                for (int c = 0; c < 8; c++) v[c] = v[c]*sc[ch+c] + sh[ch+c];
                if (skip) {
                    float sv[8] = {sPre[0].x, sPre[0].y, sPre[0].z, sPre[0].w,
                                   sPre[1].x, sPre[1].y, sPre[1].z, sPre[1].w};
#pragma unroll
                    for (int c = 0; c < 8; c++) v[c] += sv[c];
                }
#pragma unroll
                for (int c = 0; c < 8; c++) v[c] = fmaxf(v[c], 0.f);
                if (writeY) {
                    *(float4*)(writeY + (size_t)sGr*128 + kc*32 + sKs*8) =
                        make_float4(v[0], v[1], v[2], v[3]);
                    *(float4*)(writeY + (size_t)sGr*128 + kc*32 + sKs*8 + 4) =
                        make_float4(v[4], v[5], v[6], v[7]);
                }
            }
            float hi[8], lo[8];
#pragma unroll
            for (int c = 0; c < 8; c++) {
                uint32_t hb = f2tf32(v[c]);
                hi[c] = __uint_as_float(hb);
                lo[c] = __uint_as_float(f2tf32(v[c] - __uint_as_float(hb)));
            }
            // memory order within kstep row: [k0,k4,k1,k5,k2,k6,k3,k7]
            float* ph = base + sRow*40 + sKs*8;
            float* pl = ph + 5120;
            *(float4*)(ph)     = make_float4(hi[0], hi[4], hi[1], hi[5]);
            *(float4*)(ph + 4) = make_float4(hi[2], hi[6], hi[3], hi[7]);
            *(float4*)(pl)     = make_float4(lo[0], lo[4], lo[1], lo[5]);
            *(float4*)(pl + 4) = make_float4(lo[2], lo[6], lo[3], lo[7]);
        }
        // ---- STS B ----
#pragma unroll
        for (int it = 0; it < 2; it++) {
            int f = tid + it*512, n = f >> 3, q = f & 7;
            *(float4*)(base + 10240 + n*40 + q*4) = bhP[it];
            *(float4*)(base + 15360 + n*40 + q*4) = blP[it];
        }
        __syncthreads();

        // ---- prefetch next chunk (overlaps with compute below) ----
        if (kc < 3) {
            int kn = kc + 1;
            aPre[0] = make_float4(0.f,0.f,0.f,0.f);
            aPre[1] = make_float4(0.f,0.f,0.f,0.f);
            if (sGr < NN) {
                aPre[0] = *(const float4*)(Ain + aBase + kn*32);
                aPre[1] = *(const float4*)(Ain + aBase + kn*32 + 4);
                if (skip) {
                    sPre[0] = *(const float4*)(skip + aBase + kn*32);
                    sPre[1] = *(const float4*)(skip + aBase + kn*32 + 4);
                }
            }
#pragma unroll
            for (int it = 0; it < 2; it++) {
                int f = tid + it*512, n = f >> 3, q = f & 7;
                int gi = n*32 + kn*8 + q;
                bhP[it] = ((const float4*)Whi)[gi];
                blP[it] = ((const float4*)Wlo)[gi];
            }
        }

        // ---- compute 4 ksteps on this buffer ----
        float2* A2h = (float2*)base;
        float2* A2l = (float2*)(base + 5120);
        float2* B2h = (float2*)(base + 10240);
        float2* B2l = (float2*)(base + 15360);
#pragma unroll
        for (int ks = 0; ks < 4; ks++) {
            float2 ah[2][2], al[2][2];
#pragma unroll
            for (int mt = 0; mt < 2; mt++) {
                int r0 = wm*32 + mt*16 + g;
                ah[mt][0] = A2h[r0*20 + ks*4 + t];
                ah[mt][1] = A2h[(r0+8)*20 + ks*4 + t];
                al[mt][0] = A2l[r0*20 + ks*4 + t];
                al[mt][1] = A2l[(r0+8)*20 + ks*4 + t];
            }
#pragma unroll
            for (int nt = 0; nt < 4; nt++) {
                int n = wn*32 + nt*8 + g;
                float2 bh = B2h[n*20 + ks*4 + t];
                float2 bl = B2l[n*20 + ks*4 + t];
                uint32_t bh0 = __float_as_uint(bh.x), bh1 = __float_as_uint(bh.y);
                uint32_t bl0 = __float_as_uint(bl.x), bl1 = __float_as_uint(bl.y);
#pragma unroll
                for (int mt = 0; mt < 2; mt++) {
                    uint32_t a0 = __float_as_uint(ah[mt][0].x);
                    uint32_t a1 = __float_as_uint(ah[mt][1].x);
                    uint32_t a2 = __float_as_uint(ah[mt][0].y);
                    uint32_t a3 = __float_as_uint(ah[mt][1].y);
                    mma8(cfr[mt][nt], a0, a1, a2, a3, bh0, bh1);   // hi*hi
                    mma8(cfr[mt][nt], a0, a1, a2, a3, bl0, bl1);   // hi*lo
                    uint32_t l0 = __float_as_uint(al[mt][0].x);
                    uint32_t l1 = __float_as_uint(al[mt][1].x);
                    uint32_t l2 = __float_as_uint(al[mt][0].y);
                    uint32_t l3 = __float_as_uint(al[mt][1].y);
                    mma8(cfr[mt][nt], l0, l1, l2, l3, bh0, bh1);   // lo*hi
                }
            }
        }
        // no trailing sync: next iteration's STS targets the other buffer; its
        // sync orders all warps' compute(kc) (program-order before STS kc+1)
    }

    // ---- epilogue: store h + fused per-head alpha dots (head == wn) ----
#pragma unroll
    for (int mt = 0; mt < 2; mt++) {
#pragma unroll
        for (int rr = 0; rr < 2; rr++) {
            int row = bm + wm*32 + mt*16 + rr*8 + g;
            float ps = 0.f, pd = 0.f;
#pragma unroll
            for (int nt = 0; nt < 4; nt++) {
                float c0 = cfr[mt][nt][rr*2 + 0];
                float c1 = cfr[mt][nt][rr*2 + 1];
                int col0 = wn*32 + nt*8 + 2*t;
                if (row < NN)
                    *(float2*)(d_hlin + (size_t)row*128 + col0) = make_float2(c0, c1);
                ps += c0 * sAt[col0] + c1 * sAt[col0 + 1];
                pd += c0 * dAt[col0] + c1 * dAt[col0 + 1];
            }
            ps += __shfl_down_sync(0xffffffffu, ps, 2, 4);
            ps += __shfl_down_sync(0xffffffffu, ps, 1, 4);
            pd += __shfl_down_sync(0xffffffffu, pd, 2, 4);
            pd += __shfl_down_sync(0xffffffffu, pd, 1, 4);
            if (t == 0 && row < NN) {
                d_asrc[row*4 + wn] = ps;
                d_adst[row*4 + wn] = pd;
            }
        }
    }
}

// ---------------- GAT aggregation (warp per dst) + BN stats ----------------
__global__ void k_agg(const float* __restrict__ bias_l,
                      float* __restrict__ bnsum, float* __restrict__ bnsq) {
    __shared__ int   s_src[8][32];
    __shared__ float s_w[8][128];
    __shared__ float s_s1[128], s_s2[128];
    int tid = threadIdx.x;
    if (tid < 128) { s_s1[tid] = 0.f; s_s2[tid] = 0.f; }
    __syncthreads();

    int w = tid >> 5, lane = tid & 31;
    int dst = blockIdx.x * 8 + w;
    int beg = d_rowptr[dst], end = d_rowptr[dst + 1];
    int head = lane >> 3;
    float4 ad = *(const float4*)(d_adst + dst * 4);

    float4 em = make_float4(-1e30f, -1e30f, -1e30f, -1e30f);
    for (int base = beg; base < end; base += 32) {
        int idx = base + lane;
        if (idx < end) {
            int s = d_colsrc[idx];
            float4 a = *(const float4*)(d_asrc + s * 4);
            em.x = fmaxf(em.x, leaky(a.x + ad.x));
            em.y = fmaxf(em.y, leaky(a.y + ad.y));
            em.z = fmaxf(em.z, leaky(a.z + ad.z));
            em.w = fmaxf(em.w, leaky(a.w + ad.w));
        }
    }
#pragma unroll
    for (int d = 16; d; d >>= 1) {
        em.x = fmaxf(em.x, __shfl_xor_sync(0xffffffffu, em.x, d));
        em.y = fmaxf(em.y, __shfl_xor_sync(0xffffffffu, em.y, d));
        em.z = fmaxf(em.z, __shfl_xor_sync(0xffffffffu, em.z, d));
        em.w = fmaxf(em.w, __shfl_xor_sync(0xffffffffu, em.w, d));
    }

    float4 ds  = make_float4(0.f, 0.f, 0.f, 0.f);
    float4 acc = make_float4(0.f, 0.f, 0.f, 0.f);
    for (int base = beg; base < end; base += 32) {
        int idx = base + lane;
        int nE = min(32, end - base);
        if (idx < end) {
            int s = d_colsrc[idx];
            float4 a = *(const float4*)(d_asrc + s * 4);
            float4 wv;
            wv.x = __expf(leaky(a.x + ad.x) - em.x);
            wv.y = __expf(leaky(a.y + ad.y) - em.y);
            wv.z = __expf(leaky(a.z + ad.z) - em.z);
            wv.w = __expf(leaky(a.w + ad.w) - em.w);
            ds.x += wv.x; ds.y += wv.y; ds.z += wv.z; ds.w += wv.w;
            s_src[w][lane] = s;
            *(float4*)&s_w[w][lane * 4] = wv;
        }
        __syncwarp();
        const float* hb = d_hlin + lane * 4;
        int j = 0;
        for (; j + 8 <= nE; j += 8) {
            int   si[8];
            float wi[8];
            float4 hv[8];
#pragma unroll
            for (int u = 0; u < 8; u++) {
                si[u] = s_src[w][j + u];
                wi[u] = s_w[w][(j + u) * 4 + head];
            }
#pragma unroll
            for (int u = 0; u < 8; u++)
                hv[u] = *(const float4*)(hb + (size_t)si[u] * 128);
#pragma unroll
            for (int u = 0; u < 8; u++) {
                acc.x += hv[u].x * wi[u]; acc.y += hv[u].y * wi[u];
                acc.z += hv[u].z * wi[u]; acc.w += hv[u].w * wi[u];
            }
        }
        for (; j < nE; j++) {
            int s = s_src[w][j];
            float wt = s_w[w][j * 4 + head];
            float4 hv = *(const float4*)(hb + (size_t)s * 128);
            acc.x += hv.x * wt; acc.y += hv.y * wt;
            acc.z += hv.z * wt; acc.w += hv.w * wt;
        }
        __syncwarp();
    }
#pragma unroll
    for (int d = 16; d; d >>= 1) {
        ds.x += __shfl_xor_sync(0xffffffffu, ds.x, d);
        ds.y += __shfl_xor_sync(0xffffffffu, ds.y, d);
        ds.z += __shfl_xor_sync(0xffffffffu, ds.z, d);
        ds.w += __shfl_xor_sync(0xffffffffu, ds.w, d);
    }
    float dn = (head == 0) ? ds.x : (head == 1) ? ds.y : (head == 2) ? ds.z : ds.w;
    float inv = 1.0f / dn;
    float4 b4 = *(const float4*)(bias_l + lane * 4);
    float4 o = make_float4(acc.x * inv + b4.x, acc.y * inv + b4.y,
                           acc.z * inv + b4.z, acc.w * inv + b4.w);
    *(float4*)(d_bufG + (size_t)dst * 128 + lane * 4) = o;

    int c0 = lane * 4;
    atomicAdd(&s_s1[c0+0], o.x); atomicAdd(&s_s1[c0+1], o.y);
    atomicAdd(&s_s1[c0+2], o.z); atomicAdd(&s_s1[c0+3], o.w);
    atomicAdd(&s_s2[c0+0], o.x*o.x); atomicAdd(&s_s2[c0+1], o.y*o.y);
    atomicAdd(&s_s2[c0+2], o.z*o.z); atomicAdd(&s_s2[c0+3], o.w*o.w);
    __syncthreads();
    if (tid < 128) {
        atomicAdd(&bnsum[tid], s_s1[tid]);
        atomicAdd(&bnsq[tid],  s_s2[tid]);
    }
}

// ---------------- final BN apply + residual + ReLU (layer 5 only) ----------------
__global__ void k_bn(const float* __restrict__ gamma, const float* __restrict__ beta,
                     const float* __restrict__ bsum,  const float* __restrict__ bsq,
                     const float* __restrict__ skip,  float* __restrict__ out) {
    __shared__ float sc[128], sh[128];
    int tid = threadIdx.x;
    if (tid < 128) {
        float mu  = bsum[tid] * INVN;
        float var = bsq[tid] * INVN - mu * mu;
        float r = rsqrtf(var + 1e-5f);
        float gg = gamma[tid] * r;
        sc[tid] = gg;
        sh[tid] = beta[tid] - gg * mu;
    }
    __syncthreads();
    size_t g4 = (size_t)blockIdx.x * 256 + tid;
    int q = (int)(g4 & 31) * 4;
    float4 v = ((const float4*)d_bufG)[g4];
    float4 y;
    y.x = v.x * sc[q+0] + sh[q+0];
    y.y = v.y * sc[q+1] + sh[q+1];
    y.z = v.z * sc[q+2] + sh[q+2];
    y.w = v.w * sc[q+3] + sh[q+3];
    if (skip) {
        float4 s4 = ((const float4*)skip)[g4];
        y.x += s4.x; y.y += s4.y; y.z += s4.z; y.w += s4.w;
    }
    y.x = fmaxf(y.x, 0.f); y.y = fmaxf(y.y, 0.f);
    y.z = fmaxf(y.z, 0.f); y.w = fmaxf(y.w, 0.f);
    ((float4*)out)[g4] = y;
}

// ---------------- launch ----------------
extern "C" void kernel_launch(void* const* d_in, const int* in_sizes, int n_in,
                              void* d_out, int out_size) {
    const float* x       = (const float*)d_in[0];
    const int*   ei      = (const int*)  d_in[1];
    const float* Ws      = (const float*)d_in[2];
    const float* att_src = (const float*)d_in[3];
    const float* att_dst = (const float*)d_in[4];
    const float* biases  = (const float*)d_in[5];
    const float* gammas  = (const float*)d_in[6];
    const float* betas   = (const float*)d_in[7];
    float* out = (float*)d_out;

    void *pA, *pB, *pG, *pSum, *pSq, *pWh, *pWl;
    cudaGetSymbolAddress(&pA, d_bufA);
    cudaGetSymbolAddress(&pB, d_bufB);
    cudaGetSymbolAddress(&pG, d_bufG);
    cudaGetSymbolAddress(&pSum, d_bnsum);
    cudaGetSymbolAddress(&pSq,  d_bnsq);
    cudaGetSymbolAddress(&pWh,  d_whi);
    cudaGetSymbolAddress(&pWl,  d_wlo);
    float* A = (float*)pA;
    float* B = (float*)pB;
    float* G = (float*)pG;
    float* bnsum = (float*)pSum;
    float* bnsq  = (float*)pSq;
    float* whi   = (float*)pWh;
    float* wlo   = (float*)pWl;

    cudaFuncSetAttribute(k_gemm_tc, cudaFuncAttributeMaxDynamicSharedMemorySize, GSM_BYTES);

    // launch index 3 = layer-0 GEMM (ncu profiles index 3)
    k_init<<<384, 256>>>(Ws);                                    // 0
    k_count<<<(ETOT + 255) / 256, 256>>>(ei);                    // 1
    k_scan_reduce<<<NBLK_SCAN, 256>>>();                         // 2
    k_gemm_tc<<<GEMM_CTAS, 512, GSM_BYTES>>>(x, whi, wlo,        // 3  <- profiled
                                             att_src, att_dst,
                                             0, 0, 0, 0, 0, 0);
    k_scan_write<<<NBLK_SCAN, 256>>>();                          // 4
    k_scatter<<<(ETOT + 255) / 256, 256>>>(ei);                  // 5
    k_agg<<<NN / 8, 256>>>(biases, bnsum, bnsq);                 // 6 (layer 0)

    // layers 1..5: GEMM fuses BN/ReLU/skip of layer l-1
    for (int l = 1; l < NL; l++) {
        const float* skip  = (l == 4) ? B : 0;   // y3 = relu(bn3(G) + y1)
        float*       wrY   = (l == 2) ? B :      // materialize y1
                             (l == 4) ? A : 0;   // materialize y3
        k_gemm_tc<<<GEMM_CTAS, 512, GSM_BYTES>>>(G,
                                                 whi + (size_t)l * 16384,
                                                 wlo + (size_t)l * 16384,
                                                 att_src + l * 128, att_dst + l * 128,
                                                 bnsum + (l - 1) * 128, bnsq + (l - 1) * 128,
                                                 gammas + (l - 1) * 128, betas + (l - 1) * 128,
                                                 skip, wrY);
        k_agg<<<NN / 8, 256>>>(biases + l * 128, bnsum + l * 128, bnsq + l * 128);
    }

    // final output: y5 = relu(bn5(G) + y3)
    k_bn<<<NN / 8, 256>>>(gammas + 5 * 128, betas + 5 * 128,
                          bnsum + 5 * 128, bnsq + 5 * 128, A, out);
}